// round 1
// baseline (speedup 1.0000x reference)
#include <cuda_runtime.h>
#include <cuda_bf16.h>
#include <cstdint>
#include <math.h>

// Problem constants
#define BATCH   2
#define MPERB   65536          // t*n = 64*1024
#define MTOT    131072         // BATCH * MPERB
#define EDIM    512
#define TOPK    256
#define NCHUNK  128            // MTOT / 1024 (softmax partial chunks)
#define SPLITS  16             // split-K over m for GEMM2 (per batch: 65536/16 = 4096 rows each)

// Scratch (device globals: allocation-free per harness rules)
__device__ float g_scores[(size_t)MTOT * TOPK];                 // 134 MB
__device__ float g_pmax[NCHUNK * TOPK];
__device__ float g_psum[NCHUNK * TOPK];
__device__ float g_max[BATCH * TOPK];
__device__ float g_inv[BATCH * TOPK];
__device__ float g_part[(size_t)SPLITS * BATCH * TOPK * EDIM];  // 16 MB

// ---------------------------------------------------------------------------
// K1: scores[m][k] = x_flat[m][:] . W[k][:] + bias[k]
//     M = 131072, N = 256, K = 512. Tile 128x128x16, 256 threads, 8x8/thread.
// ---------------------------------------------------------------------------
__global__ __launch_bounds__(256) void k1_gemm_scores(
    const float* __restrict__ x, const float* __restrict__ W,
    const float* __restrict__ bias)
{
    __shared__ float As[16][128];   // As[kk][m]
    __shared__ float Bs[16][128];   // Bs[kk][n]

    const int tid = threadIdx.x;
    const int m0 = blockIdx.x * 128;
    const int n0 = blockIdx.y * 128;
    const int ty = tid >> 4;        // 0..15 -> m sub-rows
    const int tx = tid & 15;        // 0..15 -> n sub-cols

    float acc[8][8];
    #pragma unroll
    for (int i = 0; i < 8; i++)
        #pragma unroll
        for (int j = 0; j < 8; j++) acc[i][j] = 0.f;

    for (int kb = 0; kb < EDIM; kb += 16) {
        // Load A tile: 128 rows x 16 cols. 512 float4 total, 2 per thread.
        #pragma unroll
        for (int i = 0; i < 2; i++) {
            int f4 = tid * 2 + i;
            int row = f4 >> 2;          // 0..127
            int c4  = f4 & 3;           // 0..3 -> cols c4*4..+3
            float4 v = *reinterpret_cast<const float4*>(
                &x[(size_t)(m0 + row) * EDIM + kb + c4 * 4]);
            As[c4 * 4 + 0][row] = v.x;
            As[c4 * 4 + 1][row] = v.y;
            As[c4 * 4 + 2][row] = v.z;
            As[c4 * 4 + 3][row] = v.w;
        }
        // Load B tile: W rows n0..n0+127, cols kb..kb+15
        #pragma unroll
        for (int i = 0; i < 2; i++) {
            int f4 = tid * 2 + i;
            int row = f4 >> 2;
            int c4  = f4 & 3;
            float4 v = *reinterpret_cast<const float4*>(
                &W[(size_t)(n0 + row) * EDIM + kb + c4 * 4]);
            Bs[c4 * 4 + 0][row] = v.x;
            Bs[c4 * 4 + 1][row] = v.y;
            Bs[c4 * 4 + 2][row] = v.z;
            Bs[c4 * 4 + 3][row] = v.w;
        }
        __syncthreads();

        #pragma unroll
        for (int kk = 0; kk < 16; kk++) {
            float a[8], b[8];
            #pragma unroll
            for (int i = 0; i < 8; i++) a[i] = As[kk][ty * 8 + i];
            #pragma unroll
            for (int j = 0; j < 8; j++) b[j] = Bs[kk][tx * 8 + j];
            #pragma unroll
            for (int i = 0; i < 8; i++)
                #pragma unroll
                for (int j = 0; j < 8; j++)
                    acc[i][j] = fmaf(a[i], b[j], acc[i][j]);
        }
        __syncthreads();
    }

    // Write 8x8 with bias
    #pragma unroll
    for (int i = 0; i < 8; i++) {
        size_t rbase = (size_t)(m0 + ty * 8 + i) * TOPK + n0 + tx * 8;
        #pragma unroll
        for (int j = 0; j < 8; j += 4) {
            float4 v;
            v.x = acc[i][j + 0] + bias[n0 + tx * 8 + j + 0];
            v.y = acc[i][j + 1] + bias[n0 + tx * 8 + j + 1];
            v.z = acc[i][j + 2] + bias[n0 + tx * 8 + j + 2];
            v.w = acc[i][j + 3] + bias[n0 + tx * 8 + j + 3];
            *reinterpret_cast<float4*>(&g_scores[rbase + j]) = v;
        }
    }
}

// ---------------------------------------------------------------------------
// K2a: per-chunk online (max, sum-exp) over 1024 m rows per chunk.
//      grid = NCHUNK blocks, 256 threads (one per k).
// ---------------------------------------------------------------------------
__global__ __launch_bounds__(256) void k2a_softmax_partial()
{
    const int c = blockIdx.x;
    const int k = threadIdx.x;
    size_t base = (size_t)c * 1024 * TOPK + k;
    float mx = -INFINITY, s = 0.f;
    for (int i = 0; i < 1024; i++) {
        float v = g_scores[base + (size_t)i * TOPK];
        if (v > mx) { s = s * __expf(mx - v) + 1.0f; mx = v; }
        else        { s += __expf(v - mx); }
    }
    g_pmax[c * TOPK + k] = mx;
    g_psum[c * TOPK + k] = s;
}

// K2b: merge 64 chunk partials per (b,k); store max and 1/denominator.
__global__ __launch_bounds__(256) void k2b_softmax_merge()
{
    const int b = blockIdx.x;
    const int k = threadIdx.x;
    float mx = -INFINITY, s = 0.f;
    for (int c = b * 64; c < b * 64 + 64; c++) {
        float m2 = g_pmax[c * TOPK + k];
        float s2 = g_psum[c * TOPK + k];
        if (m2 > mx) { s = s * __expf(mx - m2) + s2; mx = m2; }
        else         { s += s2 * __expf(m2 - mx); }
    }
    g_max[b * TOPK + k] = mx;
    g_inv[b * TOPK + k] = 1.0f / s;
}

// ---------------------------------------------------------------------------
// K3: partial[s][b][k][e] = sum_{m in split s} exp(scores[m][k]-max[b][k]) * x[m][e]
//     Per batch: out tile 128(k) x 128(e), split-K over m (SPLITS chunks of 4096).
//     grid = (SPLITS, 8, BATCH): y encodes ktile(2) x etile(4).
// ---------------------------------------------------------------------------
__global__ __launch_bounds__(256) void k3_gemm_pool(const float* __restrict__ x)
{
    __shared__ float Ps[16][128];   // Ps[mstep][k] = exp weights
    __shared__ float Xs[16][128];   // Xs[mstep][e]
    __shared__ float kmax[128];

    const int tid = threadIdx.x;
    const int sp = blockIdx.x;
    const int kt = blockIdx.y >> 2;
    const int et = blockIdx.y & 3;
    const int b  = blockIdx.z;
    const int k0 = kt * 128;
    const int e0 = et * 128;
    const int mstart = b * MPERB + sp * (MPERB / SPLITS);

    if (tid < 128) kmax[tid] = g_max[b * TOPK + k0 + tid];
    __syncthreads();

    const int ty = tid >> 4;   // k sub-rows
    const int tx = tid & 15;   // e sub-cols

    float acc[8][8];
    #pragma unroll
    for (int i = 0; i < 8; i++)
        #pragma unroll
        for (int j = 0; j < 8; j++) acc[i][j] = 0.f;

    for (int mi = 0; mi < MPERB / SPLITS; mi += 16) {
        int mrow = mstart + mi;
        // Load P tile [16 m][128 k]: 512 float4, 2 per thread, exp on the fly
        #pragma unroll
        for (int i = 0; i < 2; i++) {
            int f4 = tid * 2 + i;
            int row = f4 >> 5;              // 0..15
            int c   = (f4 & 31) * 4;        // 0..124
            float4 v = *reinterpret_cast<const float4*>(
                &g_scores[(size_t)(mrow + row) * TOPK + k0 + c]);
            v.x = __expf(v.x - kmax[c + 0]);
            v.y = __expf(v.y - kmax[c + 1]);
            v.z = __expf(v.z - kmax[c + 2]);
            v.w = __expf(v.w - kmax[c + 3]);
            *reinterpret_cast<float4*>(&Ps[row][c]) = v;
        }
        // Load X tile [16 m][128 e]
        #pragma unroll
        for (int i = 0; i < 2; i++) {
            int f4 = tid * 2 + i;
            int row = f4 >> 5;
            int c   = (f4 & 31) * 4;
            float4 v = *reinterpret_cast<const float4*>(
                &x[(size_t)(mrow + row) * EDIM + e0 + c]);
            *reinterpret_cast<float4*>(&Xs[row][c]) = v;
        }
        __syncthreads();

        #pragma unroll
        for (int kk = 0; kk < 16; kk++) {
            float a[8], bb[8];
            #pragma unroll
            for (int i = 0; i < 8; i++) a[i] = Ps[kk][ty * 8 + i];
            #pragma unroll
            for (int j = 0; j < 8; j++) bb[j] = Xs[kk][tx * 8 + j];
            #pragma unroll
            for (int i = 0; i < 8; i++)
                #pragma unroll
                for (int j = 0; j < 8; j++)
                    acc[i][j] = fmaf(a[i], bb[j], acc[i][j]);
        }
        __syncthreads();
    }

    // Write partial tile
    #pragma unroll
    for (int i = 0; i < 8; i++) {
        size_t rbase = ((size_t)(sp * BATCH + b) * TOPK + (k0 + ty * 8 + i)) * EDIM
                       + e0 + tx * 8;
        #pragma unroll
        for (int j = 0; j < 8; j += 4) {
            float4 v;
            v.x = acc[i][j + 0];
            v.y = acc[i][j + 1];
            v.z = acc[i][j + 2];
            v.w = acc[i][j + 3];
            *reinterpret_cast<float4*>(&g_part[rbase + j]) = v;
        }
    }
}

// ---------------------------------------------------------------------------
// K4: out[b][k][e] = inv_den[b][k] * sum_s part[s][b][k][e]
// ---------------------------------------------------------------------------
__global__ __launch_bounds__(256) void k4_reduce(float* __restrict__ out)
{
    int idx = blockIdx.x * 256 + threadIdx.x;   // 0 .. 262143
    // idx = b*131072 + k*512 + e  (output layout)
    int b = idx >> 17;
    int k = (idx >> 9) & 255;
    float s = 0.f;
    #pragma unroll
    for (int sp = 0; sp < SPLITS; sp++)
        s += g_part[(size_t)sp * (BATCH * TOPK * EDIM) + idx];
    out[idx] = s * g_inv[b * TOPK + k];
}

// ---------------------------------------------------------------------------
extern "C" void kernel_launch(void* const* d_in, const int* in_sizes, int n_in,
                              void* d_out, int out_size)
{
    const float* x    = (const float*)d_in[0];   // [2,64,1024,512] fp32
    const float* W    = (const float*)d_in[1];   // [256,512] fp32
    const float* bias = (const float*)d_in[2];   // [256] fp32
    float* out = (float*)d_out;                  // [2,256,512] fp32

    (void)in_sizes; (void)n_in; (void)out_size;

    // K1: scores GEMM
    k1_gemm_scores<<<dim3(MTOT / 128, TOPK / 128), 256>>>(x, W, bias);
    // K2: softmax stats over token axis
    k2a_softmax_partial<<<NCHUNK, 256>>>();
    k2b_softmax_merge<<<BATCH, 256>>>();
    // K3: weighted pooling GEMM (split-K, deterministic partials)
    k3_gemm_pool<<<dim3(SPLITS, 8, BATCH), 256>>>(x);
    // K4: final reduce + normalize
    k4_reduce<<<(BATCH * TOPK * EDIM) / 256, 256>>>(out);
}

// round 5
// speedup vs baseline: 1.6502x; 1.6502x over previous
#include <cuda_runtime.h>
#include <cuda_bf16.h>
#include <cstdint>
#include <math.h>

#define BATCH 2
#define MPERB 65536
#define MTOT  131072
#define EDIM  512
#define TOPK  256
#define S3    32                 // split-m for GEMM2
#define K3M   (MPERB / S3)       // 2048

// GEMM tiling
#define TROW   80                // padded smem row bytes (64B data + 16 pad)
#define TILEB  (128 * TROW)      // 10240 per operand tile
#define STAGEB (4 * TILEB)       // Ahi, Alo, Bhi, Blo
#define SMEMB  (2 * STAGEB)      // 81920 (double buffered)

// ---------------- scratch (device globals; allocation-free) ----------------
__device__ __nv_bfloat16 g_xr_hi[(size_t)MTOT * EDIM];
__device__ __nv_bfloat16 g_xr_lo[(size_t)MTOT * EDIM];
__device__ __nv_bfloat16 g_xT_hi[(size_t)BATCH * EDIM * MPERB];
__device__ __nv_bfloat16 g_xT_lo[(size_t)BATCH * EDIM * MPERB];
__device__ __nv_bfloat16 g_w_hi[(size_t)TOPK * EDIM];
__device__ __nv_bfloat16 g_w_lo[(size_t)TOPK * EDIM];
__device__ float g_scoresT[(size_t)BATCH * TOPK * MPERB];
__device__ __nv_bfloat16 g_probs_hi[(size_t)BATCH * TOPK * MPERB];
__device__ __nv_bfloat16 g_probs_lo[(size_t)BATCH * TOPK * MPERB];
__device__ float g_inv[BATCH * TOPK];
__device__ float g_part[(size_t)S3 * BATCH * TOPK * EDIM];

// ---------------- helpers ----------------
__device__ __forceinline__ uint32_t s2u(const void* p) {
    uint32_t a;
    asm("{ .reg .u64 t; cvta.to.shared.u64 t, %1; cvt.u32.u64 %0, t; }" : "=r"(a) : "l"(p));
    return a;
}
__device__ __forceinline__ void cpa16(uint32_t dst, const void* src) {
    asm volatile("cp.async.cg.shared.global [%0], [%1], 16;" :: "r"(dst), "l"(src));
}
#define CP_COMMIT() asm volatile("cp.async.commit_group;")
#define CP_WAIT1()  asm volatile("cp.async.wait_group 1;")

// pack (a -> low16, b -> high16) bf16 hi; lo = residuals
__device__ __forceinline__ void bsplit2(float a, float b, uint32_t& hi, uint32_t& lo) {
    uint32_t h;
    asm("cvt.rn.bf16x2.f32 %0, %1, %2;" : "=r"(h) : "f"(b), "f"(a));
    float ha = __uint_as_float(h << 16);
    float hb = __uint_as_float(h & 0xFFFF0000u);
    float la = a - ha, lb = b - hb;
    asm("cvt.rn.bf16x2.f32 %0, %1, %2;" : "=r"(lo) : "f"(lb), "f"(la));
    hi = h;
}

#define LDSM4(r0, r1, r2, r3, addr) \
    asm volatile("ldmatrix.sync.aligned.m8n8.x4.shared.b16 {%0,%1,%2,%3}, [%4];" \
        : "=r"(r0), "=r"(r1), "=r"(r2), "=r"(r3) : "r"(addr))

#define MMA16816(c0, c1, c2, c3, a0, a1, a2, a3, b0, b1) \
    asm volatile("mma.sync.aligned.m16n8k16.row.col.f32.bf16.bf16.f32 " \
        "{%0,%1,%2,%3},{%4,%5,%6,%7},{%8,%9},{%0,%1,%2,%3};" \
        : "+f"(c0), "+f"(c1), "+f"(c2), "+f"(c3) \
        : "r"(a0), "r"(a1), "r"(a2), "r"(a3), "r"(b0), "r"(b1))

__device__ __forceinline__ void load_a4(uint32_t A[4][4], uint32_t off) {
    #pragma unroll
    for (int mt = 0; mt < 4; mt++)
        LDSM4(A[mt][0], A[mt][1], A[mt][2], A[mt][3], off + mt * (16 * TROW));
}
__device__ __forceinline__ void load_b4(uint32_t B[4][4], uint32_t off) {
    #pragma unroll
    for (int bt = 0; bt < 4; bt++)
        LDSM4(B[bt][0], B[bt][1], B[bt][2], B[bt][3], off + bt * (16 * TROW));
}
__device__ __forceinline__ void mma_all(float C[4][8][4], uint32_t A[4][4], uint32_t B[4][4]) {
    #pragma unroll
    for (int mt = 0; mt < 4; mt++)
        #pragma unroll
        for (int nt = 0; nt < 8; nt++)
            MMA16816(C[mt][nt][0], C[mt][nt][1], C[mt][nt][2], C[mt][nt][3],
                     A[mt][0], A[mt][1], A[mt][2], A[mt][3],
                     B[nt >> 1][(nt & 1) * 2], B[nt >> 1][(nt & 1) * 2 + 1]);
}

// one k16 step: hi*hi + lo*hi + hi*lo
__device__ __forceinline__ void compute_k16(float C[4][8][4], uint32_t stbase,
                                            uint32_t a_lane, uint32_t b_lane, int s16) {
    uint32_t aH = stbase + a_lane + s16 * 32;
    uint32_t bH = stbase + 2 * TILEB + b_lane + s16 * 32;
    uint32_t Ah[4][4], Al[4][4], Bv[4][4];
    load_a4(Ah, aH);
    load_b4(Bv, bH);
    mma_all(C, Ah, Bv);
    load_a4(Al, aH + TILEB);
    mma_all(C, Al, Bv);
    load_b4(Bv, bH + TILEB);
    mma_all(C, Ah, Bv);
}

__device__ __forceinline__ void fill_stage(uint32_t s0, int tid,
    const char* ah, const char* al, const char* bh, const char* bl,
    size_t stride, size_t koff)
{
    #pragma unroll
    for (int i = 0; i < 4; i++) {
        int idx = tid + i * 128;
        int r = idx >> 2, c = idx & 3;
        uint32_t d = s0 + r * TROW + c * 16;
        size_t go = (size_t)r * stride + koff + c * 16;
        cpa16(d,             ah + go);
        cpa16(d + TILEB,     al + go);
        cpa16(d + 2 * TILEB, bh + go);
        cpa16(d + 3 * TILEB, bl + go);
    }
    CP_COMMIT();
}

// ---------------------------------------------------------------------------
// K0: x -> row-major bf16 hi/lo  AND  m-transposed bf16 hi/lo
// ---------------------------------------------------------------------------
__global__ __launch_bounds__(256) void k0_prep(const float* __restrict__ x)
{
    __shared__ float t[64][33];
    const int tx = threadIdx.x, ty = threadIdx.y;
    const int m0 = blockIdx.x * 32, e0 = blockIdx.y * 64, b = blockIdx.z;
    const int tid = ty * 32 + tx;
    #pragma unroll
    for (int i = 0; i < 4; i++) {
        int r = ty + 8 * i;
        size_t gi = ((size_t)(b * MPERB + m0 + r)) * EDIM + e0 + tx * 2;
        float2 v = *(const float2*)&x[gi];
        uint32_t hi, lo; bsplit2(v.x, v.y, hi, lo);
        ((uint32_t*)g_xr_hi)[gi >> 1] = hi;
        ((uint32_t*)g_xr_lo)[gi >> 1] = lo;
        t[tx * 2][r] = v.x; t[tx * 2 + 1][r] = v.y;
    }
    __syncthreads();
    #pragma unroll
    for (int i = 0; i < 4; i++) {
        int f = tid + 256 * i;           // 0..1023
        int el = f >> 4, mp = f & 15;
        float v0 = t[el][mp * 2], v1 = t[el][mp * 2 + 1];
        uint32_t hi, lo; bsplit2(v0, v1, hi, lo);
        size_t go = ((size_t)(b * EDIM + e0 + el)) * MPERB + m0;
        ((uint32_t*)g_xT_hi)[(go >> 1) + mp] = hi;
        ((uint32_t*)g_xT_lo)[(go >> 1) + mp] = lo;
    }
}

__global__ __launch_bounds__(256) void k0w(const float* __restrict__ W)
{
    int r = blockIdx.x, t = threadIdx.x;
    size_t gi = (size_t)r * EDIM + t * 2;
    float2 v = *(const float2*)&W[gi];
    uint32_t hi, lo; bsplit2(v.x, v.y, hi, lo);
    ((uint32_t*)g_w_hi)[gi >> 1] = hi;
    ((uint32_t*)g_w_lo)[gi >> 1] = lo;
}

// ---------------------------------------------------------------------------
// K1: scoresT[b][k][m] = x[m][:] . W[k][:] + bias[k]   (bf16-split mma.sync)
// ---------------------------------------------------------------------------
__global__ __launch_bounds__(128) void k1_gemm(const float* __restrict__ bias)
{
    extern __shared__ char smem[];
    const uint32_t sb = s2u(smem);
    const int tid = threadIdx.x, lane = tid & 31, wid = tid >> 5;
    const int wm = wid & 1, wn = wid >> 1;
    const int m0 = blockIdx.x * 128, n0 = blockIdx.y * 128;
    const int b = m0 >> 16, ml = m0 & (MPERB - 1);

    const char* Ah_g = (const char*)g_xr_hi + (size_t)m0 * EDIM * 2;
    const char* Al_g = (const char*)g_xr_lo + (size_t)m0 * EDIM * 2;
    const char* Bh_g = (const char*)g_w_hi + (size_t)n0 * EDIM * 2;
    const char* Bl_g = (const char*)g_w_lo + (size_t)n0 * EDIM * 2;

    const uint32_t a_lane = (wm * 64 + (lane & 15)) * TROW + (lane >> 4) * 16;
    const uint32_t bmat = lane >> 3;
    const uint32_t b_lane = (wn * 64 + (bmat >> 1) * 8 + (lane & 7)) * TROW + (bmat & 1) * 16;

    float C[4][8][4];
    #pragma unroll
    for (int i = 0; i < 4; i++)
        #pragma unroll
        for (int j = 0; j < 8; j++)
            #pragma unroll
            for (int q = 0; q < 4; q++) C[i][j][q] = 0.f;

    fill_stage(sb,          tid, Ah_g, Al_g, Bh_g, Bl_g, EDIM * 2, 0);
    fill_stage(sb + STAGEB, tid, Ah_g, Al_g, Bh_g, Bl_g, EDIM * 2, 64);

    #pragma unroll 1
    for (int kb = 0; kb < 16; kb++) {
        CP_WAIT1();
        __syncthreads();
        uint32_t st = sb + (kb & 1) * STAGEB;
        compute_k16(C, st, a_lane, b_lane, 0);
        compute_k16(C, st, a_lane, b_lane, 1);
        __syncthreads();
        if (kb + 2 < 16)
            fill_stage(st, tid, Ah_g, Al_g, Bh_g, Bl_g, EDIM * 2, (size_t)(kb + 2) * 64);
        else
            CP_COMMIT();
    }

    // epilogue: transpose via smem, then coalesced rows of scoresT[k][m] + bias
    float* ts = (float*)smem;   // [128 k][128 m]
    #pragma unroll
    for (int mt = 0; mt < 4; mt++)
        #pragma unroll
        for (int nt = 0; nt < 8; nt++) {
            int i0 = wm * 64 + mt * 16 + (lane >> 2);
            int j0 = wn * 64 + nt * 8 + (lane & 3) * 2;
            ts[(j0    ) * 128 + i0    ] = C[mt][nt][0];
            ts[(j0 + 1) * 128 + i0    ] = C[mt][nt][1];
            ts[(j0    ) * 128 + i0 + 8] = C[mt][nt][2];
            ts[(j0 + 1) * 128 + i0 + 8] = C[mt][nt][3];
        }
    __syncthreads();
    #pragma unroll 1
    for (int it = 0; it < 32; it++) {
        int j = it * 4 + (tid >> 5);
        int c = (tid & 31) * 4;
        float4 v = *(float4*)&ts[j * 128 + c];
        float bv = bias[n0 + j];
        v.x += bv; v.y += bv; v.z += bv; v.w += bv;
        *(float4*)&g_scoresT[((size_t)(b * TOPK + n0 + j)) * MPERB + ml + c] = v;
    }
}

// ---------------------------------------------------------------------------
// K2: per (b,k) row softmax stats; write probs hi/lo bf16 + 1/denominator
// ---------------------------------------------------------------------------
__global__ __launch_bounds__(256) void k2_softmax()
{
    const int rowid = blockIdx.x;
    const float4* p4 = (const float4*)(g_scoresT + (size_t)rowid * MPERB);
    const int t = threadIdx.x;
    __shared__ float red[256];

    float mx = -INFINITY;
    for (int i = 0; i < 64; i++) {
        float4 v = p4[i * 256 + t];
        mx = fmaxf(mx, fmaxf(fmaxf(v.x, v.y), fmaxf(v.z, v.w)));
    }
    red[t] = mx; __syncthreads();
    for (int o = 128; o; o >>= 1) { if (t < o) red[t] = fmaxf(red[t], red[t + o]); __syncthreads(); }
    mx = red[0]; __syncthreads();

    uint2* ph = (uint2*)(g_probs_hi + (size_t)rowid * MPERB);
    uint2* pl = (uint2*)(g_probs_lo + (size_t)rowid * MPERB);
    float s = 0.f;
    for (int i = 0; i < 64; i++) {
        float4 v = p4[i * 256 + t];
        v.x = __expf(v.x - mx); v.y = __expf(v.y - mx);
        v.z = __expf(v.z - mx); v.w = __expf(v.w - mx);
        s += (v.x + v.y) + (v.z + v.w);
        uint2 h, l;
        bsplit2(v.x, v.y, h.x, l.x);
        bsplit2(v.z, v.w, h.y, l.y);
        ph[i * 256 + t] = h; pl[i * 256 + t] = l;
    }
    red[t] = s; __syncthreads();
    for (int o = 128; o; o >>= 1) { if (t < o) red[t] += red[t + o]; __syncthreads(); }
    if (t == 0) g_inv[rowid] = 1.0f / red[0];
}

// ---------------------------------------------------------------------------
// K3: part[sp][b][k][e] = sum_{m in split} probs[k][m] * xT[e][m]
// ---------------------------------------------------------------------------
__global__ __launch_bounds__(128) void k3_gemm()
{
    extern __shared__ char smem[];
    const uint32_t sb = s2u(smem);
    const int tid = threadIdx.x, lane = tid & 31, wid = tid >> 5;
    const int wm = wid & 1, wn = wid >> 1;
    const int kt = blockIdx.x >> 2, et = blockIdx.x & 3;
    const int sp = blockIdx.y, b = blockIdx.z;

    const size_t aoff = (((size_t)(b * TOPK + kt * 128)) * MPERB + (size_t)sp * K3M) * 2;
    const size_t boff = (((size_t)(b * EDIM + et * 128)) * MPERB + (size_t)sp * K3M) * 2;
    const char* Ah_g = (const char*)g_probs_hi + aoff;
    const char* Al_g = (const char*)g_probs_lo + aoff;
    const char* Bh_g = (const char*)g_xT_hi + boff;
    const char* Bl_g = (const char*)g_xT_lo + boff;

    const uint32_t a_lane = (wm * 64 + (lane & 15)) * TROW + (lane >> 4) * 16;
    const uint32_t bmat = lane >> 3;
    const uint32_t b_lane = (wn * 64 + (bmat >> 1) * 8 + (lane & 7)) * TROW + (bmat & 1) * 16;

    float C[4][8][4];
    #pragma unroll
    for (int i = 0; i < 4; i++)
        #pragma unroll
        for (int j = 0; j < 8; j++)
            #pragma unroll
            for (int q = 0; q < 4; q++) C[i][j][q] = 0.f;

    fill_stage(sb,          tid, Ah_g, Al_g, Bh_g, Bl_g, (size_t)MPERB * 2, 0);
    fill_stage(sb + STAGEB, tid, Ah_g, Al_g, Bh_g, Bl_g, (size_t)MPERB * 2, 64);

    #pragma unroll 1
    for (int kb = 0; kb < K3M / 32; kb++) {      // 64 stages
        CP_WAIT1();
        __syncthreads();
        uint32_t st = sb + (kb & 1) * STAGEB;
        compute_k16(C, st, a_lane, b_lane, 0);
        compute_k16(C, st, a_lane, b_lane, 1);
        __syncthreads();
        if (kb + 2 < K3M / 32)
            fill_stage(st, tid, Ah_g, Al_g, Bh_g, Bl_g, (size_t)MPERB * 2,
                       (size_t)(kb + 2) * 64);
        else
            CP_COMMIT();
    }

    // epilogue: direct store of partials [k][e]
    #pragma unroll
    for (int mt = 0; mt < 4; mt++)
        #pragma unroll
        for (int nt = 0; nt < 8; nt++) {
            int i0 = wm * 64 + mt * 16 + (lane >> 2);
            int j0 = wn * 64 + nt * 8 + (lane & 3) * 2;
            float* dst = g_part + ((size_t)((sp * BATCH + b) * TOPK) + kt * 128 + i0) * EDIM
                         + et * 128 + j0;
            float2 v0; v0.x = C[mt][nt][0]; v0.y = C[mt][nt][1];
            float2 v1; v1.x = C[mt][nt][2]; v1.y = C[mt][nt][3];
            *(float2*)dst = v0;
            *(float2*)(dst + (size_t)8 * EDIM) = v1;
        }
}

// ---------------------------------------------------------------------------
// K4: out[b][k][e] = inv[b][k] * sum_sp part[sp][b][k][e]
// ---------------------------------------------------------------------------
__global__ __launch_bounds__(256) void k4_reduce(float* __restrict__ out)
{
    const int idx = blockIdx.x * 256 + threadIdx.x;
    const int b = idx >> 17;
    const int k = (idx >> 9) & 255;
    const int off = idx & 0x1FFFF;
    float s = 0.f;
    #pragma unroll
    for (int sp = 0; sp < S3; sp++)
        s += g_part[((size_t)(sp * BATCH + b) << 17) + off];
    out[idx] = s * g_inv[(b << 8) | k];
}

// ---------------------------------------------------------------------------
extern "C" void kernel_launch(void* const* d_in, const int* in_sizes, int n_in,
                              void* d_out, int out_size)
{
    const float* x    = (const float*)d_in[0];
    const float* W    = (const float*)d_in[1];
    const float* bias = (const float*)d_in[2];
    float* out = (float*)d_out;
    (void)in_sizes; (void)n_in; (void)out_size;

    cudaFuncSetAttribute(k1_gemm, cudaFuncAttributeMaxDynamicSharedMemorySize, SMEMB);
    cudaFuncSetAttribute(k3_gemm, cudaFuncAttributeMaxDynamicSharedMemorySize, SMEMB);

    k0_prep<<<dim3(MPERB / 32, EDIM / 64, BATCH), dim3(32, 8)>>>(x);
    k0w<<<TOPK, 256>>>(W);
    k1_gemm<<<dim3(MTOT / 128, TOPK / 128), 128, SMEMB>>>(bias);
    k2_softmax<<<BATCH * TOPK, 256>>>();
    k3_gemm<<<dim3(8, S3, BATCH), 128, SMEMB>>>();
    k4_reduce<<<(BATCH * TOPK * EDIM) / 256, 256>>>(out);
}

// round 6
// speedup vs baseline: 2.5001x; 1.5150x over previous
#include <cuda_runtime.h>
#include <cuda_bf16.h>
#include <cstdint>
#include <math.h>

#define BATCH 2
#define MPERB 65536
#define MTOT  131072
#define EDIM  512
#define TOPK  256
#define S3    32
#define K3M   2048
#define TROW  80

// k1 smem stage layout
#define K1_AS    0
#define K1_AL    10240
#define K1_BH    20480
#define K1_BL    40960
#define K1_AF    61440
#define K1_STAGE 79872
#define SMEM1    (2 * K1_STAGE)      // 159744

// k3 smem stage layout
#define K3_AH    0
#define K3_AL    10240
#define K3_BH    20480
#define K3_BL    30720
#define K3_BF    40960
#define K3_STAGE 57344
#define SMEM3    (2 * K3_STAGE)      // 114688

// ---------------- scratch ----------------
__device__ __nv_bfloat16 g_w_hi[TOPK * EDIM];
__device__ __nv_bfloat16 g_w_lo[TOPK * EDIM];
__device__ float g_scoresT[(size_t)BATCH * TOPK * MPERB];
__device__ __nv_bfloat16 g_probs_hi[(size_t)BATCH * TOPK * MPERB];
__device__ __nv_bfloat16 g_probs_lo[(size_t)BATCH * TOPK * MPERB];
__device__ float g_pmax[(size_t)BATCH * TOPK * 512];
__device__ float g_max[BATCH * TOPK];
__device__ float g_inv[BATCH * TOPK];
__device__ float g_part[(size_t)S3 * BATCH * TOPK * EDIM];

// ---------------- helpers ----------------
__device__ __forceinline__ uint32_t s2u(const void* p) {
    uint32_t a;
    asm("{ .reg .u64 t; cvta.to.shared.u64 t, %1; cvt.u32.u64 %0, t; }" : "=r"(a) : "l"(p));
    return a;
}
__device__ __forceinline__ void cpa16(uint32_t dst, const void* src) {
    asm volatile("cp.async.cg.shared.global [%0], [%1], 16;" :: "r"(dst), "l"(src));
}
#define CP_COMMIT() asm volatile("cp.async.commit_group;")
#define CP_WAIT1()  asm volatile("cp.async.wait_group 1;")

__device__ __forceinline__ void bsplit2(float a, float b, uint32_t& hi, uint32_t& lo) {
    uint32_t h;
    asm("cvt.rn.bf16x2.f32 %0, %1, %2;" : "=r"(h) : "f"(b), "f"(a));
    float ha = __uint_as_float(h << 16);
    float hb = __uint_as_float(h & 0xFFFF0000u);
    float la = a - ha, lb = b - hb;
    asm("cvt.rn.bf16x2.f32 %0, %1, %2;" : "=r"(lo) : "f"(lb), "f"(la));
    hi = h;
}

#define LDSM4(r0, r1, r2, r3, addr) \
    asm volatile("ldmatrix.sync.aligned.m8n8.x4.shared.b16 {%0,%1,%2,%3}, [%4];" \
        : "=r"(r0), "=r"(r1), "=r"(r2), "=r"(r3) : "r"(addr))

#define MMA16816(c0, c1, c2, c3, a0, a1, a2, a3, b0, b1) \
    asm volatile("mma.sync.aligned.m16n8k16.row.col.f32.bf16.bf16.f32 " \
        "{%0,%1,%2,%3},{%4,%5,%6,%7},{%8,%9},{%0,%1,%2,%3};" \
        : "+f"(c0), "+f"(c1), "+f"(c2), "+f"(c3) \
        : "r"(a0), "r"(a1), "r"(a2), "r"(a3), "r"(b0), "r"(b1))

__device__ __forceinline__ void ldsmA(uint32_t A[4][4], uint32_t off) {
    #pragma unroll
    for (int mt = 0; mt < 4; mt++)
        LDSM4(A[mt][0], A[mt][1], A[mt][2], A[mt][3], off + mt * (16 * TROW));
}
__device__ __forceinline__ void ldsmB4(uint32_t B[4][4], uint32_t off) {
    #pragma unroll
    for (int bt = 0; bt < 4; bt++)
        LDSM4(B[bt][0], B[bt][1], B[bt][2], B[bt][3], off + bt * (16 * TROW));
}
__device__ __forceinline__ void ldsmB2(uint32_t B[2][4], uint32_t off) {
    #pragma unroll
    for (int bt = 0; bt < 2; bt++)
        LDSM4(B[bt][0], B[bt][1], B[bt][2], B[bt][3], off + bt * (16 * TROW));
}
__device__ __forceinline__ void mma8(float C[4][8][4], uint32_t A[4][4], uint32_t B[4][4]) {
    #pragma unroll
    for (int mt = 0; mt < 4; mt++)
        #pragma unroll
        for (int nt = 0; nt < 8; nt++)
            MMA16816(C[mt][nt][0], C[mt][nt][1], C[mt][nt][2], C[mt][nt][3],
                     A[mt][0], A[mt][1], A[mt][2], A[mt][3],
                     B[nt >> 1][(nt & 1) * 2], B[nt >> 1][(nt & 1) * 2 + 1]);
}
__device__ __forceinline__ void mma4(float C[4][4][4], uint32_t A[4][4], uint32_t B[2][4]) {
    #pragma unroll
    for (int mt = 0; mt < 4; mt++)
        #pragma unroll
        for (int nt = 0; nt < 4; nt++)
            MMA16816(C[mt][nt][0], C[mt][nt][1], C[mt][nt][2], C[mt][nt][3],
                     A[mt][0], A[mt][1], A[mt][2], A[mt][3],
                     B[nt >> 1][(nt & 1) * 2], B[nt >> 1][(nt & 1) * 2 + 1]);
}

// ---------------------------------------------------------------------------
// K0w: W fp32 -> bf16 hi/lo
// ---------------------------------------------------------------------------
__global__ __launch_bounds__(256) void k0w(const float* __restrict__ W)
{
    int r = blockIdx.x, t = threadIdx.x;
    size_t gi = (size_t)r * EDIM + t * 2;
    float2 v = *(const float2*)&W[gi];
    uint32_t hi, lo; bsplit2(v.x, v.y, hi, lo);
    ((uint32_t*)g_w_hi)[gi >> 1] = hi;
    ((uint32_t*)g_w_lo)[gi >> 1] = lo;
}

// ---------------------------------------------------------------------------
// K1: scoresT[b][k][m] = x[m][:] . W[k][:] + bias[k]; also pmax[k][mtile]
//     CTA 128m x 256n, 8 warps (64x64), x fp32 converted in smem.
// ---------------------------------------------------------------------------
__global__ __launch_bounds__(256) void k1_gemm(const float* __restrict__ x,
                                               const float* __restrict__ bias)
{
    extern __shared__ char smem[];
    const uint32_t sb = s2u(smem);
    const int tid = threadIdx.x, lane = tid & 31, wid = tid >> 5;
    const int wm = wid & 1, wn = wid >> 1;
    const int m0 = blockIdx.x * 128;
    const int b = m0 >> 16, ml = m0 & 65535;

    const uint32_t a_lane = (wm * 64 + (lane & 15)) * TROW + (lane >> 4) * 16;
    const uint32_t bmat = lane >> 3;
    const uint32_t b_lane = (wn * 64 + (bmat >> 1) * 8 + (lane & 7)) * TROW + (bmat & 1) * 16;

    float C[4][8][4];
    #pragma unroll
    for (int i = 0; i < 4; i++)
        #pragma unroll
        for (int j = 0; j < 8; j++)
            #pragma unroll
            for (int q = 0; q < 4; q++) C[i][j][q] = 0.f;

    auto fill = [&](int s, int kb) {
        uint32_t st = sb + s * K1_STAGE;
        const char* bh = (const char*)g_w_hi;
        const char* bl = (const char*)g_w_lo;
        #pragma unroll
        for (int i = 0; i < 4; i++) {
            int idx = tid + i * 256;
            int r = idx >> 2, c = idx & 3;
            size_t go = ((size_t)r * EDIM + kb * 32) * 2 + c * 16;
            cpa16(st + K1_BH + r * TROW + c * 16, bh + go);
            cpa16(st + K1_BL + r * TROW + c * 16, bl + go);
        }
        #pragma unroll
        for (int i = 0; i < 4; i++) {
            int idx = tid + i * 256;
            int r = idx >> 3, c = idx & 7;
            cpa16(st + K1_AF + r * 144 + c * 16,
                  (const char*)x + ((size_t)(m0 + r) * EDIM + kb * 32) * 4 + c * 16);
        }
        CP_COMMIT();
    };

    auto convertA = [&](int s) {
        const float* af = (const float*)(smem + s * K1_STAGE + K1_AF + (tid & 127) * 144)
                          + (tid >> 7) * 16;
        float4 f0 = *(const float4*)af;
        float4 f1 = *(const float4*)(af + 4);
        float4 f2 = *(const float4*)(af + 8);
        float4 f3 = *(const float4*)(af + 12);
        uint32_t h[8], l[8];
        bsplit2(f0.x, f0.y, h[0], l[0]); bsplit2(f0.z, f0.w, h[1], l[1]);
        bsplit2(f1.x, f1.y, h[2], l[2]); bsplit2(f1.z, f1.w, h[3], l[3]);
        bsplit2(f2.x, f2.y, h[4], l[4]); bsplit2(f2.z, f2.w, h[5], l[5]);
        bsplit2(f3.x, f3.y, h[6], l[6]); bsplit2(f3.z, f3.w, h[7], l[7]);
        uint4* dh = (uint4*)(smem + s * K1_STAGE + K1_AS + (tid & 127) * TROW + (tid >> 7) * 32);
        dh[0] = make_uint4(h[0], h[1], h[2], h[3]);
        dh[1] = make_uint4(h[4], h[5], h[6], h[7]);
        uint4* dl = (uint4*)(smem + s * K1_STAGE + K1_AL + (tid & 127) * TROW + (tid >> 7) * 32);
        dl[0] = make_uint4(l[0], l[1], l[2], l[3]);
        dl[1] = make_uint4(l[4], l[5], l[6], l[7]);
    };

    fill(0, 0); fill(1, 1);
    #pragma unroll 1
    for (int kb = 0; kb < 16; kb++) {
        int s = kb & 1;
        CP_WAIT1();
        __syncthreads();
        convertA(s);
        __syncthreads();
        uint32_t st = sb + s * K1_STAGE;
        #pragma unroll
        for (int s16 = 0; s16 < 2; s16++) {
            uint32_t Ah[4][4], Al[4][4], Bv[4][4];
            ldsmA(Ah, st + K1_AS + a_lane + s16 * 32);
            ldsmB4(Bv, st + K1_BH + b_lane + s16 * 32);
            mma8(C, Ah, Bv);
            ldsmA(Al, st + K1_AL + a_lane + s16 * 32);
            mma8(C, Al, Bv);
            ldsmB4(Bv, st + K1_BL + b_lane + s16 * 32);
            mma8(C, Ah, Bv);
        }
        __syncthreads();
        if (kb + 2 < 16) fill(s, kb + 2);
        else CP_COMMIT();
    }

    // epilogue: per 64-k chunk, transpose via smem, add bias, row max, store
    float* ts = (float*)smem;   // [64 k][132 m]
    #pragma unroll 1
    for (int c = 0; c < 4; c++) {
        if (wn == c) {
            #pragma unroll
            for (int mt = 0; mt < 4; mt++)
                #pragma unroll
                for (int nt = 0; nt < 8; nt++) {
                    int i0 = wm * 64 + mt * 16 + (lane >> 2);
                    int j0 = nt * 8 + (lane & 3) * 2;
                    ts[j0 * 132 + i0]           = C[mt][nt][0];
                    ts[(j0 + 1) * 132 + i0]     = C[mt][nt][1];
                    ts[j0 * 132 + i0 + 8]       = C[mt][nt][2];
                    ts[(j0 + 1) * 132 + i0 + 8] = C[mt][nt][3];
                }
        }
        __syncthreads();
        #pragma unroll
        for (int it = 0; it < 8; it++) {
            int j = it * 8 + (tid >> 5);
            int kg = c * 64 + j;
            float4 v = *(float4*)&ts[j * 132 + lane * 4];
            float bv = bias[kg];
            v.x += bv; v.y += bv; v.z += bv; v.w += bv;
            float mx = fmaxf(fmaxf(v.x, v.y), fmaxf(v.z, v.w));
            #pragma unroll
            for (int o = 16; o; o >>= 1)
                mx = fmaxf(mx, __shfl_xor_sync(0xffffffffu, mx, o));
            if (lane == 0)
                g_pmax[(size_t)(b * TOPK + kg) * 512 + (ml >> 7)] = mx;
            *(float4*)&g_scoresT[(size_t)(b * TOPK + kg) * MPERB + ml + lane * 4] = v;
        }
        __syncthreads();
    }
}

// ---------------------------------------------------------------------------
// K2a: merge 512 partial maxes per (b,k)
// ---------------------------------------------------------------------------
__global__ __launch_bounds__(128) void k2a_merge()
{
    const int row = blockIdx.x, t = threadIdx.x;
    float4 v = ((const float4*)(g_pmax + (size_t)row * 512))[t];
    float mx = fmaxf(fmaxf(v.x, v.y), fmaxf(v.z, v.w));
    __shared__ float red[128];
    red[t] = mx; __syncthreads();
    for (int o = 64; o; o >>= 1) {
        if (t < o) red[t] = fmaxf(red[t], red[t + o]);
        __syncthreads();
    }
    if (t == 0) g_max[row] = red[0];
}

// ---------------------------------------------------------------------------
// K2: single pass: probs = exp(s - max) as bf16 hi/lo; 1/sum
// ---------------------------------------------------------------------------
__global__ __launch_bounds__(256) void k2_softmax()
{
    const int row = blockIdx.x, t = threadIdx.x;
    const float mx = g_max[row];
    const float4* p4 = (const float4*)(g_scoresT + (size_t)row * MPERB);
    uint2* ph = (uint2*)(g_probs_hi + (size_t)row * MPERB);
    uint2* pl = (uint2*)(g_probs_lo + (size_t)row * MPERB);
    __shared__ float red[256];

    float s = 0.f;
    for (int i = 0; i < 64; i++) {
        float4 v = p4[i * 256 + t];
        v.x = __expf(v.x - mx); v.y = __expf(v.y - mx);
        v.z = __expf(v.z - mx); v.w = __expf(v.w - mx);
        s += (v.x + v.y) + (v.z + v.w);
        uint2 h, l;
        bsplit2(v.x, v.y, h.x, l.x);
        bsplit2(v.z, v.w, h.y, l.y);
        ph[i * 256 + t] = h; pl[i * 256 + t] = l;
    }
    red[t] = s; __syncthreads();
    for (int o = 128; o; o >>= 1) {
        if (t < o) red[t] += red[t + o];
        __syncthreads();
    }
    if (t == 0) g_inv[row] = 1.0f / red[0];
}

// ---------------------------------------------------------------------------
// K3: part[sp][b][k][e] = sum_m probs[k][m] * x[m][e]
//     CTA 128k x 128e, 8 warps (64x32), B = x fp32 transposed+split in smem.
// ---------------------------------------------------------------------------
__global__ __launch_bounds__(256) void k3_gemm(const float* __restrict__ x)
{
    extern __shared__ char smem[];
    const uint32_t sb = s2u(smem);
    const int tid = threadIdx.x, lane = tid & 31, wid = tid >> 5;
    const int wm = wid & 1, wn = wid >> 1;
    const int kt = blockIdx.x >> 2, et = blockIdx.x & 3;
    const int sp = blockIdx.y, b = blockIdx.z;
    const int k0 = kt * 128, e0 = et * 128;
    const size_t mstart = (size_t)sp * K3M;

    const uint32_t a_lane = (wm * 64 + (lane & 15)) * TROW + (lane >> 4) * 16;
    const uint32_t bmat = lane >> 3;
    const uint32_t b_lane = (wn * 32 + (bmat >> 1) * 8 + (lane & 7)) * TROW + (bmat & 1) * 16;

    float C[4][4][4];
    #pragma unroll
    for (int i = 0; i < 4; i++)
        #pragma unroll
        for (int j = 0; j < 4; j++)
            #pragma unroll
            for (int q = 0; q < 4; q++) C[i][j][q] = 0.f;

    auto fill = [&](int s, int kb) {
        uint32_t st = sb + s * K3_STAGE;
        const char* ah = (const char*)g_probs_hi;
        const char* al = (const char*)g_probs_lo;
        #pragma unroll
        for (int i = 0; i < 2; i++) {
            int idx = tid + i * 256;
            int r = idx >> 2, c = idx & 3;
            size_t go = ((size_t)(b * TOPK + k0 + r) * MPERB + mstart + kb * 32) * 2 + c * 16;
            cpa16(st + K3_AH + r * TROW + c * 16, ah + go);
            cpa16(st + K3_AL + r * TROW + c * 16, al + go);
        }
        #pragma unroll
        for (int i = 0; i < 4; i++) {
            int idx = tid + i * 256;
            int r = idx >> 5, c = idx & 31;
            size_t gm = (size_t)b * MPERB + mstart + kb * 32 + r;
            cpa16(st + K3_BF + r * 512 + c * 16,
                  (const char*)x + (gm * EDIM + e0) * 4 + c * 16);
        }
        CP_COMMIT();
    };

    auto convertB = [&](int s) {
        const int n = tid & 127, h = tid >> 7;
        const float* bf = (const float*)(smem + s * K3_STAGE + K3_BF);
        float f[16];
        #pragma unroll
        for (int kk = 0; kk < 16; kk++)
            f[kk] = bf[(h * 16 + kk) * 128 + n];
        uint32_t hh[8], ll[8];
        #pragma unroll
        for (int j = 0; j < 8; j++)
            bsplit2(f[2 * j], f[2 * j + 1], hh[j], ll[j]);
        uint4* dh = (uint4*)(smem + s * K3_STAGE + K3_BH + n * TROW + h * 32);
        dh[0] = make_uint4(hh[0], hh[1], hh[2], hh[3]);
        dh[1] = make_uint4(hh[4], hh[5], hh[6], hh[7]);
        uint4* dl = (uint4*)(smem + s * K3_STAGE + K3_BL + n * TROW + h * 32);
        dl[0] = make_uint4(ll[0], ll[1], ll[2], ll[3]);
        dl[1] = make_uint4(ll[4], ll[5], ll[6], ll[7]);
    };

    fill(0, 0); fill(1, 1);
    #pragma unroll 1
    for (int kb = 0; kb < K3M / 32; kb++) {
        int s = kb & 1;
        CP_WAIT1();
        __syncthreads();
        convertB(s);
        __syncthreads();
        uint32_t st = sb + s * K3_STAGE;
        #pragma unroll
        for (int s16 = 0; s16 < 2; s16++) {
            uint32_t Ah[4][4], Al[4][4], Bv[2][4];
            ldsmA(Ah, st + K3_AH + a_lane + s16 * 32);
            ldsmB2(Bv, st + K3_BH + b_lane + s16 * 32);
            mma4(C, Ah, Bv);
            ldsmA(Al, st + K3_AL + a_lane + s16 * 32);
            mma4(C, Al, Bv);
            ldsmB2(Bv, st + K3_BL + b_lane + s16 * 32);
            mma4(C, Ah, Bv);
        }
        __syncthreads();
        if (kb + 2 < K3M / 32) fill(s, kb + 2);
        else CP_COMMIT();
    }

    // epilogue: direct [k][e] partial store
    #pragma unroll
    for (int mt = 0; mt < 4; mt++)
        #pragma unroll
        for (int nt = 0; nt < 4; nt++) {
            int i0 = wm * 64 + mt * 16 + (lane >> 2);
            int j0 = wn * 32 + nt * 8 + (lane & 3) * 2;
            float* dst = g_part + ((size_t)(sp * BATCH + b) * TOPK + k0 + i0) * EDIM
                         + e0 + j0;
            float2 v0; v0.x = C[mt][nt][0]; v0.y = C[mt][nt][1];
            float2 v1; v1.x = C[mt][nt][2]; v1.y = C[mt][nt][3];
            *(float2*)dst = v0;
            *(float2*)(dst + (size_t)8 * EDIM) = v1;
        }
}

// ---------------------------------------------------------------------------
// K4: out = inv * sum partials
// ---------------------------------------------------------------------------
__global__ __launch_bounds__(256) void k4_reduce(float* __restrict__ out)
{
    const int idx = blockIdx.x * 256 + threadIdx.x;
    const int b = idx >> 17;
    const int k = (idx >> 9) & 255;
    const int off = idx & 0x1FFFF;
    float s = 0.f;
    #pragma unroll
    for (int sp = 0; sp < S3; sp++)
        s += g_part[((size_t)(sp * BATCH + b) << 17) + off];
    out[idx] = s * g_inv[(b << 8) | k];
}

// ---------------------------------------------------------------------------
extern "C" void kernel_launch(void* const* d_in, const int* in_sizes, int n_in,
                              void* d_out, int out_size)
{
    const float* x    = (const float*)d_in[0];
    const float* W    = (const float*)d_in[1];
    const float* bias = (const float*)d_in[2];
    float* out = (float*)d_out;
    (void)in_sizes; (void)n_in; (void)out_size;

    cudaFuncSetAttribute(k1_gemm, cudaFuncAttributeMaxDynamicSharedMemorySize, SMEM1);
    cudaFuncSetAttribute(k3_gemm, cudaFuncAttributeMaxDynamicSharedMemorySize, SMEM3);

    k0w<<<TOPK, 256>>>(W);
    k1_gemm<<<MTOT / 128, 256, SMEM1>>>(x, bias);
    k2a_merge<<<BATCH * TOPK, 128>>>();
    k2_softmax<<<BATCH * TOPK, 256>>>();
    k3_gemm<<<dim3(8, S3, BATCH), 256, SMEM3>>>(x);
    k4_reduce<<<(BATCH * TOPK * EDIM) / 256, 256>>>(out);
}

// round 9
// speedup vs baseline: 2.5060x; 1.0024x over previous
#include <cuda_runtime.h>
#include <cuda_bf16.h>
#include <cstdint>
#include <math.h>

#define BATCH 2
#define MPERB 65536
#define MTOT  131072
#define EDIM  512
#define TOPK  256
#define S3    32
#define K3M   2048
#define TROW  80

// k1 smem: B (W hi/lo) 3 stages, then A (x split) 2 stages; epilogue reuses front
#define K1_BSTG 40960                    // 256 rows * 80 * 2 (hi+lo)
#define K1_A0   (3 * K1_BSTG)            // 122880
#define K1_ASTG 20480                    // 128 rows * 80 * 2
#define SMEM1   (K1_A0 + 2 * K1_ASTG)    // 163840

// k3 smem: A (probs hi/lo) 3 stages, then B (x split) 2 stages
#define K3_ASTG 20480                    // 128 rows * 80 * 2
#define K3_B0   (3 * K3_ASTG)            // 61440
#define K3_BSTG 20480                    // 128 rows * 80 * 2
#define SMEM3   (K3_B0 + 2 * K3_BSTG)    // 102400

// ---------------- scratch ----------------
__device__ __nv_bfloat16 g_w_hi[TOPK * EDIM];
__device__ __nv_bfloat16 g_w_lo[TOPK * EDIM];
__device__ __nv_bfloat16 g_ph[(size_t)BATCH * TOPK * MPERB];
__device__ __nv_bfloat16 g_pl[(size_t)BATCH * TOPK * MPERB];
__device__ float g_psum[(size_t)BATCH * TOPK * 512];
__device__ float g_inv[BATCH * TOPK];
__device__ float g_part[(size_t)S3 * BATCH * TOPK * EDIM];

// ---------------- helpers ----------------
__device__ __forceinline__ uint32_t s2u(const void* p) {
    uint32_t a;
    asm("{ .reg .u64 t; cvta.to.shared.u64 t, %1; cvt.u32.u64 %0, t; }" : "=r"(a) : "l"(p));
    return a;
}
__device__ __forceinline__ void cpa16(uint32_t dst, const void* src) {
    asm volatile("cp.async.cg.shared.global [%0], [%1], 16;" :: "r"(dst), "l"(src));
}
#define CP_COMMIT() asm volatile("cp.async.commit_group;")
#define CP_WAIT1()  asm volatile("cp.async.wait_group 1;")

__device__ __forceinline__ void bsplit2(float a, float b, uint32_t& hi, uint32_t& lo) {
    uint32_t h;
    asm("cvt.rn.bf16x2.f32 %0, %1, %2;" : "=r"(h) : "f"(b), "f"(a));
    float ha = __uint_as_float(h << 16);
    float hb = __uint_as_float(h & 0xFFFF0000u);
    float la = a - ha, lb = b - hb;
    asm("cvt.rn.bf16x2.f32 %0, %1, %2;" : "=r"(lo) : "f"(lb), "f"(la));
    hi = h;
}

#define LDSM4(r0, r1, r2, r3, addr) \
    asm volatile("ldmatrix.sync.aligned.m8n8.x4.shared.b16 {%0,%1,%2,%3}, [%4];" \
        : "=r"(r0), "=r"(r1), "=r"(r2), "=r"(r3) : "r"(addr))

#define MMA16816(c0, c1, c2, c3, a0, a1, a2, a3, b0, b1) \
    asm volatile("mma.sync.aligned.m16n8k16.row.col.f32.bf16.bf16.f32 " \
        "{%0,%1,%2,%3},{%4,%5,%6,%7},{%8,%9},{%0,%1,%2,%3};" \
        : "+f"(c0), "+f"(c1), "+f"(c2), "+f"(c3) \
        : "r"(a0), "r"(a1), "r"(a2), "r"(a3), "r"(b0), "r"(b1))

__device__ __forceinline__ void ldsmA(uint32_t A[4][4], uint32_t off) {
    #pragma unroll
    for (int mt = 0; mt < 4; mt++)
        LDSM4(A[mt][0], A[mt][1], A[mt][2], A[mt][3], off + mt * (16 * TROW));
}
__device__ __forceinline__ void ldsmB4(uint32_t B[4][4], uint32_t off) {
    #pragma unroll
    for (int bt = 0; bt < 4; bt++)
        LDSM4(B[bt][0], B[bt][1], B[bt][2], B[bt][3], off + bt * (16 * TROW));
}
__device__ __forceinline__ void ldsmB2(uint32_t B[2][4], uint32_t off) {
    #pragma unroll
    for (int bt = 0; bt < 2; bt++)
        LDSM4(B[bt][0], B[bt][1], B[bt][2], B[bt][3], off + bt * (16 * TROW));
}
__device__ __forceinline__ void mma8(float C[4][8][4], uint32_t A[4][4], uint32_t B[4][4]) {
    #pragma unroll
    for (int mt = 0; mt < 4; mt++)
        #pragma unroll
        for (int nt = 0; nt < 8; nt++)
            MMA16816(C[mt][nt][0], C[mt][nt][1], C[mt][nt][2], C[mt][nt][3],
                     A[mt][0], A[mt][1], A[mt][2], A[mt][3],
                     B[nt >> 1][(nt & 1) * 2], B[nt >> 1][(nt & 1) * 2 + 1]);
}
__device__ __forceinline__ void mma4(float C[4][4][4], uint32_t A[4][4], uint32_t B[2][4]) {
    #pragma unroll
    for (int mt = 0; mt < 4; mt++)
        #pragma unroll
        for (int nt = 0; nt < 4; nt++)
            MMA16816(C[mt][nt][0], C[mt][nt][1], C[mt][nt][2], C[mt][nt][3],
                     A[mt][0], A[mt][1], A[mt][2], A[mt][3],
                     B[nt >> 1][(nt & 1) * 2], B[nt >> 1][(nt & 1) * 2 + 1]);
}

// ---------------------------------------------------------------------------
// K0w: W fp32 -> bf16 hi/lo
// ---------------------------------------------------------------------------
__global__ __launch_bounds__(256) void k0w(const float* __restrict__ W)
{
    int r = blockIdx.x, t = threadIdx.x;
    size_t gi = (size_t)r * EDIM + t * 2;
    float2 v = *(const float2*)&W[gi];
    uint32_t hi, lo; bsplit2(v.x, v.y, hi, lo);
    ((uint32_t*)g_w_hi)[gi >> 1] = hi;
    ((uint32_t*)g_w_lo)[gi >> 1] = lo;
}

// ---------------------------------------------------------------------------
// K1: s = x.W^T + bias; epilogue: p = exp(s) -> probs hi/lo + per-tile psum
//     CTA 128m x 256n, 8 warps (64x64). A via LDG->split->STS, B via cp.async.
// ---------------------------------------------------------------------------
__global__ __launch_bounds__(256) void k1_gemm(const float* __restrict__ x,
                                               const float* __restrict__ bias)
{
    extern __shared__ char smem[];
    const uint32_t sb = s2u(smem);
    const int tid = threadIdx.x, lane = tid & 31, wid = tid >> 5;
    const int wm = wid & 1, wn = wid >> 1;
    const int m0 = blockIdx.x * 128;
    const int b = m0 >> 16, ml = m0 & 65535;

    const uint32_t a_lane = (wm * 64 + (lane & 15)) * TROW + (lane >> 4) * 16;
    const uint32_t bmat = lane >> 3;
    const uint32_t b_lane = (wn * 64 + (bmat >> 1) * 8 + (lane & 7)) * TROW + (bmat & 1) * 16;

    float C[4][8][4];
    #pragma unroll
    for (int i = 0; i < 4; i++)
        #pragma unroll
        for (int j = 0; j < 8; j++)
            #pragma unroll
            for (int q = 0; q < 4; q++) C[i][j][q] = 0.f;

    // A prefetch regs: row = tid>>1, k-half = tid&1 (16 floats)
    const int ar = tid >> 1, ahalf = tid & 1;
    const float* axp = x + (size_t)(m0 + ar) * EDIM + ahalf * 16;
    float4 a4[4];

    auto ldgA = [&](int kb) {
        const float4* p = (const float4*)(axp + kb * 32);
        a4[0] = p[0]; a4[1] = p[1]; a4[2] = p[2]; a4[3] = p[3];
    };
    auto stsA = [&](int s) {
        uint32_t h[8], l[8];
        bsplit2(a4[0].x, a4[0].y, h[0], l[0]); bsplit2(a4[0].z, a4[0].w, h[1], l[1]);
        bsplit2(a4[1].x, a4[1].y, h[2], l[2]); bsplit2(a4[1].z, a4[1].w, h[3], l[3]);
        bsplit2(a4[2].x, a4[2].y, h[4], l[4]); bsplit2(a4[2].z, a4[2].w, h[5], l[5]);
        bsplit2(a4[3].x, a4[3].y, h[6], l[6]); bsplit2(a4[3].z, a4[3].w, h[7], l[7]);
        char* d = smem + K1_A0 + s * K1_ASTG + ar * TROW + ahalf * 32;
        ((uint4*)d)[0] = make_uint4(h[0], h[1], h[2], h[3]);
        ((uint4*)d)[1] = make_uint4(h[4], h[5], h[6], h[7]);
        char* dl = d + 10240;
        ((uint4*)dl)[0] = make_uint4(l[0], l[1], l[2], l[3]);
        ((uint4*)dl)[1] = make_uint4(l[4], l[5], l[6], l[7]);
    };
    auto fillB = [&](int s, int kb) {
        uint32_t st = sb + s * K1_BSTG;
        #pragma unroll
        for (int i = 0; i < 4; i++) {
            int idx = tid + i * 256;
            int r = idx >> 2, c = idx & 3;
            size_t go = ((size_t)r * EDIM + kb * 32) * 2 + c * 16;
            cpa16(st + r * TROW + c * 16, (const char*)g_w_hi + go);
            cpa16(st + 20480 + r * TROW + c * 16, (const char*)g_w_lo + go);
        }
        CP_COMMIT();
    };

    ldgA(0); fillB(0, 0); fillB(1, 1); stsA(0); ldgA(1);

    #pragma unroll 1
    for (int kb = 0; kb < 16; kb++) {
        CP_WAIT1();
        __syncthreads();
        if (kb < 14) fillB((kb + 2) % 3, kb + 2); else CP_COMMIT();
        if (kb < 15) stsA((kb + 1) & 1);
        if (kb < 14) ldgA(kb + 2);
        uint32_t sa = sb + K1_A0 + (kb & 1) * K1_ASTG;
        uint32_t sB = sb + (kb % 3) * K1_BSTG;
        #pragma unroll
        for (int s16 = 0; s16 < 2; s16++) {
            uint32_t Ah[4][4], Al[4][4], Bv[4][4];
            ldsmA(Ah, sa + a_lane + s16 * 32);
            ldsmB4(Bv, sB + b_lane + s16 * 32);
            mma8(C, Ah, Bv);
            ldsmA(Al, sa + 10240 + a_lane + s16 * 32);
            mma8(C, Al, Bv);
            ldsmB4(Bv, sB + 20480 + b_lane + s16 * 32);
            mma8(C, Ah, Bv);
        }
    }
    __syncthreads();

    // epilogue: per 64-n chunk, transpose via smem, exp, psum, bf16-split store
    float* ts = (float*)smem;   // [64 k][132 m]
    #pragma unroll 1
    for (int c = 0; c < 4; c++) {
        if (wn == c) {
            #pragma unroll
            for (int mt = 0; mt < 4; mt++)
                #pragma unroll
                for (int nt = 0; nt < 8; nt++) {
                    int i0 = wm * 64 + mt * 16 + (lane >> 2);
                    int j0 = nt * 8 + (lane & 3) * 2;
                    ts[j0 * 132 + i0]           = C[mt][nt][0];
                    ts[(j0 + 1) * 132 + i0]     = C[mt][nt][1];
                    ts[j0 * 132 + i0 + 8]       = C[mt][nt][2];
                    ts[(j0 + 1) * 132 + i0 + 8] = C[mt][nt][3];
                }
        }
        __syncthreads();
        #pragma unroll
        for (int it = 0; it < 8; it++) {
            int j = it * 8 + wid;
            int kg = c * 64 + j;
            float4 v = *(float4*)&ts[j * 132 + lane * 4];
            float bv = bias[kg];
            v.x = __expf(v.x + bv); v.y = __expf(v.y + bv);
            v.z = __expf(v.z + bv); v.w = __expf(v.w + bv);
            float s = (v.x + v.y) + (v.z + v.w);
            #pragma unroll
            for (int o = 16; o; o >>= 1)
                s += __shfl_xor_sync(0xffffffffu, s, o);
            size_t rowb = (size_t)(b * TOPK + kg);
            if (lane == 0)
                g_psum[rowb * 512 + (ml >> 7)] = s;
            uint2 h, l;
            bsplit2(v.x, v.y, h.x, l.x);
            bsplit2(v.z, v.w, h.y, l.y);
            size_t eo = (rowb * MPERB + ml) * 2 + lane * 8;
            *(uint2*)((char*)g_ph + eo) = h;
            *(uint2*)((char*)g_pl + eo) = l;
        }
        __syncthreads();
    }
}

// ---------------------------------------------------------------------------
// K2a: denom per (b,k) = sum of 512 tile psums -> 1/denom
// ---------------------------------------------------------------------------
__global__ __launch_bounds__(128) void k2a()
{
    const int row = blockIdx.x, t = threadIdx.x;
    float4 v = ((const float4*)(g_psum + (size_t)row * 512))[t];
    float s = (v.x + v.y) + (v.z + v.w);
    __shared__ float red[128];
    red[t] = s; __syncthreads();
    for (int o = 64; o; o >>= 1) {
        if (t < o) red[t] += red[t + o];
        __syncthreads();
    }
    if (t == 0) g_inv[row] = 1.0f / red[0];
}

// ---------------------------------------------------------------------------
// K3: part[sp][b][k][e] = sum_m probs[k][m] * x[m][e]
//     CTA 128k x 128e, 8 warps (64x32). A via cp.async, B via LDG->split->STS.
// ---------------------------------------------------------------------------
__global__ __launch_bounds__(256) void k3_gemm(const float* __restrict__ x)
{
    extern __shared__ char smem[];
    const uint32_t sb = s2u(smem);
    const int tid = threadIdx.x, lane = tid & 31, wid = tid >> 5;
    const int wm = wid & 1, wn = wid >> 1;
    const int kt = blockIdx.x >> 2, et = blockIdx.x & 3;
    const int sp = blockIdx.y, b = blockIdx.z;
    const int k0 = kt * 128;
    const size_t mstart = (size_t)sp * K3M;

    const uint32_t a_lane = (wm * 64 + (lane & 15)) * TROW + (lane >> 4) * 16;
    const uint32_t bmat = lane >> 3;
    const uint32_t b_lane = (wn * 32 + (bmat >> 1) * 8 + (lane & 7)) * TROW + (bmat & 1) * 16;

    float C[4][4][4];
    #pragma unroll
    for (int i = 0; i < 4; i++)
        #pragma unroll
        for (int j = 0; j < 4; j++)
            #pragma unroll
            for (int q = 0; q < 4; q++) C[i][j][q] = 0.f;

    // B prefetch: 2 m-rows x 8 e per thread
    const int m2 = (tid & 15) * 2, eg = tid >> 4;
    const float* bxp = x + ((size_t)b * MPERB + mstart + m2) * EDIM + et * 128 + eg * 8;
    float4 b4[4];

    auto ldgB = [&](int kb) {
        const float4* p = (const float4*)(bxp + (size_t)kb * 32 * EDIM);
        b4[0] = p[0]; b4[1] = p[1];
        const float4* q = (const float4*)((const float*)p + EDIM);
        b4[2] = q[0]; b4[3] = q[1];
    };
    auto stsB = [&](int s) {
        float f0[8] = {b4[0].x, b4[0].y, b4[0].z, b4[0].w, b4[1].x, b4[1].y, b4[1].z, b4[1].w};
        float f1[8] = {b4[2].x, b4[2].y, b4[2].z, b4[2].w, b4[3].x, b4[3].y, b4[3].z, b4[3].w};
        char* base = smem + K3_B0 + s * K3_BSTG;
        #pragma unroll
        for (int j = 0; j < 8; j++) {
            uint32_t h, l;
            bsplit2(f0[j], f1[j], h, l);
            *(uint32_t*)(base + (eg * 8 + j) * TROW + m2 * 2) = h;
            *(uint32_t*)(base + 10240 + (eg * 8 + j) * TROW + m2 * 2) = l;
        }
    };
    auto fillA = [&](int s, int kb) {
        uint32_t st = sb + s * K3_ASTG;
        #pragma unroll
        for (int i = 0; i < 2; i++) {
            int idx = tid + i * 256;
            int r = idx >> 2, c = idx & 3;
            size_t go = ((size_t)(b * TOPK + k0 + r) * MPERB + mstart + kb * 32) * 2 + c * 16;
            cpa16(st + r * TROW + c * 16, (const char*)g_ph + go);
            cpa16(st + 10240 + r * TROW + c * 16, (const char*)g_pl + go);
        }
        CP_COMMIT();
    };

    ldgB(0); fillA(0, 0); fillA(1, 1); stsB(0); ldgB(1);

    #pragma unroll 1
    for (int kb = 0; kb < 64; kb++) {
        CP_WAIT1();
        __syncthreads();
        if (kb < 62) fillA((kb + 2) % 3, kb + 2); else CP_COMMIT();
        if (kb < 63) stsB((kb + 1) & 1);
        if (kb < 62) ldgB(kb + 2);
        uint32_t sa = sb + (kb % 3) * K3_ASTG;
        uint32_t sB = sb + K3_B0 + (kb & 1) * K3_BSTG;
        #pragma unroll
        for (int s16 = 0; s16 < 2; s16++) {
            uint32_t Ah[4][4], Al[4][4], Bv[2][4];
            ldsmA(Ah, sa + a_lane + s16 * 32);
            ldsmB2(Bv, sB + b_lane + s16 * 32);
            mma4(C, Ah, Bv);
            ldsmA(Al, sa + 10240 + a_lane + s16 * 32);
            mma4(C, Al, Bv);
            ldsmB2(Bv, sB + 10240 + b_lane + s16 * 32);
            mma4(C, Ah, Bv);
        }
    }

    // epilogue: direct [k][e] partial store
    #pragma unroll
    for (int mt = 0; mt < 4; mt++)
        #pragma unroll
        for (int nt = 0; nt < 4; nt++) {
            int i0 = wm * 64 + mt * 16 + (lane >> 2);
            int j0 = wn * 32 + nt * 8 + (lane & 3) * 2;
            float* dst = g_part + ((size_t)(sp * BATCH + b) * TOPK + k0 + i0) * EDIM
                         + et * 128 + j0;
            float2 v0; v0.x = C[mt][nt][0]; v0.y = C[mt][nt][1];
            float2 v1; v1.x = C[mt][nt][2]; v1.y = C[mt][nt][3];
            *(float2*)dst = v0;
            *(float2*)(dst + (size_t)8 * EDIM) = v1;
        }
}

// ---------------------------------------------------------------------------
// K4: out = inv * sum partials
// ---------------------------------------------------------------------------
__global__ __launch_bounds__(256) void k4_reduce(float* __restrict__ out)
{
    const int idx = blockIdx.x * 256 + threadIdx.x;
    const int b = idx >> 17;
    const int k = (idx >> 9) & 255;
    const int off = idx & 0x1FFFF;
    float s = 0.f;
    #pragma unroll
    for (int sp = 0; sp < S3; sp++)
        s += g_part[((size_t)(sp * BATCH + b) << 17) + off];
    out[idx] = s * g_inv[(b << 8) | k];
}

// ---------------------------------------------------------------------------
extern "C" void kernel_launch(void* const* d_in, const int* in_sizes, int n_in,
                              void* d_out, int out_size)
{
    const float* x    = (const float*)d_in[0];
    const float* W    = (const float*)d_in[1];
    const float* bias = (const float*)d_in[2];
    float* out = (float*)d_out;
    (void)in_sizes; (void)n_in; (void)out_size;

    cudaFuncSetAttribute(k1_gemm, cudaFuncAttributeMaxDynamicSharedMemorySize, SMEM1);
    cudaFuncSetAttribute(k3_gemm, cudaFuncAttributeMaxDynamicSharedMemorySize, SMEM3);

    k0w<<<TOPK, 256>>>(W);
    k1_gemm<<<MTOT / 128, 256, SMEM1>>>(x, bias);
    k2a<<<BATCH * TOPK, 128>>>();
    k3_gemm<<<dim3(8, S3, BATCH), 256, SMEM3>>>(x);
    k4_reduce<<<(BATCH * TOPK * EDIM) / 256, 256>>>(out);
}

// round 10
// speedup vs baseline: 2.5832x; 1.0308x over previous
#include <cuda_runtime.h>
#include <cuda_bf16.h>
#include <cstdint>
#include <math.h>

#define BATCH 2
#define MPERB 65536
#define MTOT  131072
#define EDIM  512
#define TOPK  256
#define S3    32
#define K3M   2048
#define TROW  80

// k1 smem: B (W hi/lo) 3 stages, then A (x split) 2 stages; epilogue reuses front
#define K1_BSTG 40960                    // 256 rows * 80 * 2 (hi+lo)
#define K1_A0   (3 * K1_BSTG)            // 122880
#define K1_ASTG 20480                    // 128 rows * 80 * 2
#define SMEM1   (K1_A0 + 2 * K1_ASTG)    // 163840

// k3 smem: A (probs hi/lo) 3 stages, then B (x split) 2 stages
#define K3_ASTG 20480                    // 128 rows * 80 * 2
#define K3_B0   (3 * K3_ASTG)            // 61440
#define K3_BSTG 20480                    // 128 rows * 80 * 2
#define SMEM3   (K3_B0 + 2 * K3_BSTG)    // 102400

// ---------------- scratch ----------------
__device__ __nv_bfloat16 g_w_hi[TOPK * EDIM];
__device__ __nv_bfloat16 g_w_lo[TOPK * EDIM];
__device__ __nv_bfloat16 g_ph[(size_t)BATCH * TOPK * MPERB];
__device__ __nv_bfloat16 g_pl[(size_t)BATCH * TOPK * MPERB];
__device__ float g_psum[(size_t)BATCH * TOPK * 512];
__device__ float g_inv[BATCH * TOPK];
__device__ float g_part[(size_t)S3 * BATCH * TOPK * EDIM];

// ---------------- helpers ----------------
__device__ __forceinline__ uint32_t s2u(const void* p) {
    uint32_t a;
    asm("{ .reg .u64 t; cvta.to.shared.u64 t, %1; cvt.u32.u64 %0, t; }" : "=r"(a) : "l"(p));
    return a;
}
__device__ __forceinline__ void cpa16(uint32_t dst, const void* src) {
    asm volatile("cp.async.cg.shared.global [%0], [%1], 16;" :: "r"(dst), "l"(src));
}
#define CP_COMMIT() asm volatile("cp.async.commit_group;")
#define CP_WAIT1()  asm volatile("cp.async.wait_group 1;")

__device__ __forceinline__ void bsplit2(float a, float b, uint32_t& hi, uint32_t& lo) {
    uint32_t h;
    asm("cvt.rn.bf16x2.f32 %0, %1, %2;" : "=r"(h) : "f"(b), "f"(a));
    float ha = __uint_as_float(h << 16);
    float hb = __uint_as_float(h & 0xFFFF0000u);
    float la = a - ha, lb = b - hb;
    asm("cvt.rn.bf16x2.f32 %0, %1, %2;" : "=r"(lo) : "f"(lb), "f"(la));
    hi = h;
}

#define LDSM4(r0, r1, r2, r3, addr) \
    asm volatile("ldmatrix.sync.aligned.m8n8.x4.shared.b16 {%0,%1,%2,%3}, [%4];" \
        : "=r"(r0), "=r"(r1), "=r"(r2), "=r"(r3) : "r"(addr))

#define MMA16816(c0, c1, c2, c3, a0, a1, a2, a3, b0, b1) \
    asm volatile("mma.sync.aligned.m16n8k16.row.col.f32.bf16.bf16.f32 " \
        "{%0,%1,%2,%3},{%4,%5,%6,%7},{%8,%9},{%0,%1,%2,%3};" \
        : "+f"(c0), "+f"(c1), "+f"(c2), "+f"(c3) \
        : "r"(a0), "r"(a1), "r"(a2), "r"(a3), "r"(b0), "r"(b1))

__device__ __forceinline__ void ldsmA(uint32_t A[4][4], uint32_t off) {
    #pragma unroll
    for (int mt = 0; mt < 4; mt++)
        LDSM4(A[mt][0], A[mt][1], A[mt][2], A[mt][3], off + mt * (16 * TROW));
}
__device__ __forceinline__ void ldsmB4(uint32_t B[4][4], uint32_t off) {
    #pragma unroll
    for (int bt = 0; bt < 4; bt++)
        LDSM4(B[bt][0], B[bt][1], B[bt][2], B[bt][3], off + bt * (16 * TROW));
}
__device__ __forceinline__ void ldsmB2(uint32_t B[2][4], uint32_t off) {
    #pragma unroll
    for (int bt = 0; bt < 2; bt++)
        LDSM4(B[bt][0], B[bt][1], B[bt][2], B[bt][3], off + bt * (16 * TROW));
}
__device__ __forceinline__ void mma8(float C[4][8][4], uint32_t A[4][4], uint32_t B[4][4]) {
    #pragma unroll
    for (int mt = 0; mt < 4; mt++)
        #pragma unroll
        for (int nt = 0; nt < 8; nt++)
            MMA16816(C[mt][nt][0], C[mt][nt][1], C[mt][nt][2], C[mt][nt][3],
                     A[mt][0], A[mt][1], A[mt][2], A[mt][3],
                     B[nt >> 1][(nt & 1) * 2], B[nt >> 1][(nt & 1) * 2 + 1]);
}
__device__ __forceinline__ void mma4(float C[4][4][4], uint32_t A[4][4], uint32_t B[2][4]) {
    #pragma unroll
    for (int mt = 0; mt < 4; mt++)
        #pragma unroll
        for (int nt = 0; nt < 4; nt++)
            MMA16816(C[mt][nt][0], C[mt][nt][1], C[mt][nt][2], C[mt][nt][3],
                     A[mt][0], A[mt][1], A[mt][2], A[mt][3],
                     B[nt >> 1][(nt & 1) * 2], B[nt >> 1][(nt & 1) * 2 + 1]);
}

// ---------------------------------------------------------------------------
// K0w: W fp32 -> bf16 hi/lo
// ---------------------------------------------------------------------------
__global__ __launch_bounds__(256) void k0w(const float* __restrict__ W)
{
    int r = blockIdx.x, t = threadIdx.x;
    size_t gi = (size_t)r * EDIM + t * 2;
    float2 v = *(const float2*)&W[gi];
    uint32_t hi, lo; bsplit2(v.x, v.y, hi, lo);
    ((uint32_t*)g_w_hi)[gi >> 1] = hi;
    ((uint32_t*)g_w_lo)[gi >> 1] = lo;
}

// ---------------------------------------------------------------------------
// K1: s = x.W^T + bias; epilogue: p = exp(s) -> probs hi/lo + per-tile psum
//     CTA 128m x 256n, 8 warps (64x64). A via LDG->split->STS, B via cp.async.
// ---------------------------------------------------------------------------
__global__ __launch_bounds__(256) void k1_gemm(const float* __restrict__ x,
                                               const float* __restrict__ bias)
{
    extern __shared__ char smem[];
    const uint32_t sb = s2u(smem);
    const int tid = threadIdx.x, lane = tid & 31, wid = tid >> 5;
    const int wm = wid & 1, wn = wid >> 1;
    const int m0 = blockIdx.x * 128;
    const int b = m0 >> 16, ml = m0 & 65535;

    const uint32_t a_lane = (wm * 64 + (lane & 15)) * TROW + (lane >> 4) * 16;
    const uint32_t bmat = lane >> 3;
    const uint32_t b_lane = (wn * 64 + (bmat >> 1) * 8 + (lane & 7)) * TROW + (bmat & 1) * 16;

    float C[4][8][4];
    #pragma unroll
    for (int i = 0; i < 4; i++)
        #pragma unroll
        for (int j = 0; j < 8; j++)
            #pragma unroll
            for (int q = 0; q < 4; q++) C[i][j][q] = 0.f;

    // A prefetch regs: row = tid>>1, k-half = tid&1 (16 floats)
    const int ar = tid >> 1, ahalf = tid & 1;
    const float* axp = x + (size_t)(m0 + ar) * EDIM + ahalf * 16;
    float4 a4[4];

    auto ldgA = [&](int kb) {
        const float4* p = (const float4*)(axp + kb * 32);
        a4[0] = p[0]; a4[1] = p[1]; a4[2] = p[2]; a4[3] = p[3];
    };
    auto stsA = [&](int s) {
        uint32_t h[8], l[8];
        bsplit2(a4[0].x, a4[0].y, h[0], l[0]); bsplit2(a4[0].z, a4[0].w, h[1], l[1]);
        bsplit2(a4[1].x, a4[1].y, h[2], l[2]); bsplit2(a4[1].z, a4[1].w, h[3], l[3]);
        bsplit2(a4[2].x, a4[2].y, h[4], l[4]); bsplit2(a4[2].z, a4[2].w, h[5], l[5]);
        bsplit2(a4[3].x, a4[3].y, h[6], l[6]); bsplit2(a4[3].z, a4[3].w, h[7], l[7]);
        char* d = smem + K1_A0 + s * K1_ASTG + ar * TROW + ahalf * 32;
        ((uint4*)d)[0] = make_uint4(h[0], h[1], h[2], h[3]);
        ((uint4*)d)[1] = make_uint4(h[4], h[5], h[6], h[7]);
        char* dl = d + 10240;
        ((uint4*)dl)[0] = make_uint4(l[0], l[1], l[2], l[3]);
        ((uint4*)dl)[1] = make_uint4(l[4], l[5], l[6], l[7]);
    };
    auto fillB = [&](int s, int kb) {
        uint32_t st = sb + s * K1_BSTG;
        #pragma unroll
        for (int i = 0; i < 4; i++) {
            int idx = tid + i * 256;
            int r = idx >> 2, c = idx & 3;
            size_t go = ((size_t)r * EDIM + kb * 32) * 2 + c * 16;
            cpa16(st + r * TROW + c * 16, (const char*)g_w_hi + go);
            cpa16(st + 20480 + r * TROW + c * 16, (const char*)g_w_lo + go);
        }
        CP_COMMIT();
    };

    ldgA(0); fillB(0, 0); fillB(1, 1); stsA(0); ldgA(1);

    #pragma unroll 1
    for (int kb = 0; kb < 16; kb++) {
        CP_WAIT1();
        __syncthreads();
        if (kb < 14) fillB((kb + 2) % 3, kb + 2); else CP_COMMIT();
        if (kb < 15) stsA((kb + 1) & 1);
        if (kb < 14) ldgA(kb + 2);
        uint32_t sa = sb + K1_A0 + (kb & 1) * K1_ASTG;
        uint32_t sB = sb + (kb % 3) * K1_BSTG;
        #pragma unroll
        for (int s16 = 0; s16 < 2; s16++) {
            uint32_t Ah[4][4], Al[4][4], Bv[4][4];
            ldsmA(Ah, sa + a_lane + s16 * 32);
            ldsmB4(Bv, sB + b_lane + s16 * 32);
            mma8(C, Ah, Bv);
            ldsmA(Al, sa + 10240 + a_lane + s16 * 32);
            mma8(C, Al, Bv);
            ldsmB4(Bv, sB + 20480 + b_lane + s16 * 32);
            mma8(C, Ah, Bv);
        }
    }
    __syncthreads();

    // epilogue: per 64-n chunk, transpose via smem, exp, psum, bf16-split store
    float* ts = (float*)smem;   // [64 k][132 m]
    #pragma unroll 1
    for (int c = 0; c < 4; c++) {
        if (wn == c) {
            #pragma unroll
            for (int mt = 0; mt < 4; mt++)
                #pragma unroll
                for (int nt = 0; nt < 8; nt++) {
                    int i0 = wm * 64 + mt * 16 + (lane >> 2);
                    int j0 = nt * 8 + (lane & 3) * 2;
                    ts[j0 * 132 + i0]           = C[mt][nt][0];
                    ts[(j0 + 1) * 132 + i0]     = C[mt][nt][1];
                    ts[j0 * 132 + i0 + 8]       = C[mt][nt][2];
                    ts[(j0 + 1) * 132 + i0 + 8] = C[mt][nt][3];
                }
        }
        __syncthreads();
        #pragma unroll
        for (int it = 0; it < 8; it++) {
            int j = it * 8 + wid;
            int kg = c * 64 + j;
            float4 v = *(float4*)&ts[j * 132 + lane * 4];
            float bv = bias[kg];
            v.x = __expf(v.x + bv); v.y = __expf(v.y + bv);
            v.z = __expf(v.z + bv); v.w = __expf(v.w + bv);
            float s = (v.x + v.y) + (v.z + v.w);
            #pragma unroll
            for (int o = 16; o; o >>= 1)
                s += __shfl_xor_sync(0xffffffffu, s, o);
            size_t rowb = (size_t)(b * TOPK + kg);
            if (lane == 0)
                g_psum[rowb * 512 + (ml >> 7)] = s;
            uint2 h, l;
            bsplit2(v.x, v.y, h.x, l.x);
            bsplit2(v.z, v.w, h.y, l.y);
            size_t eo = (rowb * MPERB + ml) * 2 + lane * 8;
            *(uint2*)((char*)g_ph + eo) = h;
            *(uint2*)((char*)g_pl + eo) = l;
        }
        __syncthreads();
    }
}

// ---------------------------------------------------------------------------
// K2a: denom per (b,k) = sum of 512 tile psums -> 1/denom
// ---------------------------------------------------------------------------
__global__ __launch_bounds__(128) void k2a()
{
    const int row = blockIdx.x, t = threadIdx.x;
    float4 v = ((const float4*)(g_psum + (size_t)row * 512))[t];
    float s = (v.x + v.y) + (v.z + v.w);
    __shared__ float red[128];
    red[t] = s; __syncthreads();
    for (int o = 64; o; o >>= 1) {
        if (t < o) red[t] += red[t + o];
        __syncthreads();
    }
    if (t == 0) g_inv[row] = 1.0f / red[0];
}

// ---------------------------------------------------------------------------
// K3: part[sp][b][k][e] = sum_m probs[k][m] * x[m][e]
//     CTA 128k x 128e, 8 warps (64x32). A via cp.async, B via LDG->split->STS.
//     launch_bounds(256,2): cap regs at 128 so TWO CTAs co-reside per SM.
// ---------------------------------------------------------------------------
__global__ __launch_bounds__(256, 2) void k3_gemm(const float* __restrict__ x)
{
    extern __shared__ char smem[];
    const uint32_t sb = s2u(smem);
    const int tid = threadIdx.x, lane = tid & 31, wid = tid >> 5;
    const int wm = wid & 1, wn = wid >> 1;
    const int kt = blockIdx.x >> 2, et = blockIdx.x & 3;
    const int sp = blockIdx.y, b = blockIdx.z;
    const int k0 = kt * 128;
    const size_t mstart = (size_t)sp * K3M;

    const uint32_t a_lane = (wm * 64 + (lane & 15)) * TROW + (lane >> 4) * 16;
    const uint32_t bmat = lane >> 3;
    const uint32_t b_lane = (wn * 32 + (bmat >> 1) * 8 + (lane & 7)) * TROW + (bmat & 1) * 16;

    float C[4][4][4];
    #pragma unroll
    for (int i = 0; i < 4; i++)
        #pragma unroll
        for (int j = 0; j < 4; j++)
            #pragma unroll
            for (int q = 0; q < 4; q++) C[i][j][q] = 0.f;

    // B prefetch: 2 m-rows x 8 e per thread
    const int m2 = (tid & 15) * 2, eg = tid >> 4;
    const float* bxp = x + ((size_t)b * MPERB + mstart + m2) * EDIM + et * 128 + eg * 8;
    float4 b4[4];

    auto ldgB = [&](int kb) {
        const float4* p = (const float4*)(bxp + (size_t)kb * 32 * EDIM);
        b4[0] = p[0]; b4[1] = p[1];
        const float4* q = (const float4*)((const float*)p + EDIM);
        b4[2] = q[0]; b4[3] = q[1];
    };
    auto stsB = [&](int s) {
        float f0[8] = {b4[0].x, b4[0].y, b4[0].z, b4[0].w, b4[1].x, b4[1].y, b4[1].z, b4[1].w};
        float f1[8] = {b4[2].x, b4[2].y, b4[2].z, b4[2].w, b4[3].x, b4[3].y, b4[3].z, b4[3].w};
        char* base = smem + K3_B0 + s * K3_BSTG;
        #pragma unroll
        for (int j = 0; j < 8; j++) {
            uint32_t h, l;
            bsplit2(f0[j], f1[j], h, l);
            *(uint32_t*)(base + (eg * 8 + j) * TROW + m2 * 2) = h;
            *(uint32_t*)(base + 10240 + (eg * 8 + j) * TROW + m2 * 2) = l;
        }
    };
    auto fillA = [&](int s, int kb) {
        uint32_t st = sb + s * K3_ASTG;
        #pragma unroll
        for (int i = 0; i < 2; i++) {
            int idx = tid + i * 256;
            int r = idx >> 2, c = idx & 3;
            size_t go = ((size_t)(b * TOPK + k0 + r) * MPERB + mstart + kb * 32) * 2 + c * 16;
            cpa16(st + r * TROW + c * 16, (const char*)g_ph + go);
            cpa16(st + 10240 + r * TROW + c * 16, (const char*)g_pl + go);
        }
        CP_COMMIT();
    };

    ldgB(0); fillA(0, 0); fillA(1, 1); stsB(0); ldgB(1);

    #pragma unroll 1
    for (int kb = 0; kb < 64; kb++) {
        CP_WAIT1();
        __syncthreads();
        if (kb < 62) fillA((kb + 2) % 3, kb + 2); else CP_COMMIT();
        if (kb < 63) stsB((kb + 1) & 1);
        if (kb < 62) ldgB(kb + 2);
        uint32_t sa = sb + (kb % 3) * K3_ASTG;
        uint32_t sB = sb + K3_B0 + (kb & 1) * K3_BSTG;
        #pragma unroll
        for (int s16 = 0; s16 < 2; s16++) {
            uint32_t Ah[4][4], Al[4][4], Bv[2][4];
            ldsmA(Ah, sa + a_lane + s16 * 32);
            ldsmB2(Bv, sB + b_lane + s16 * 32);
            mma4(C, Ah, Bv);
            ldsmA(Al, sa + 10240 + a_lane + s16 * 32);
            mma4(C, Al, Bv);
            ldsmB2(Bv, sB + 10240 + b_lane + s16 * 32);
            mma4(C, Ah, Bv);
        }
    }

    // epilogue: direct [k][e] partial store
    #pragma unroll
    for (int mt = 0; mt < 4; mt++)
        #pragma unroll
        for (int nt = 0; nt < 4; nt++) {
            int i0 = wm * 64 + mt * 16 + (lane >> 2);
            int j0 = wn * 32 + nt * 8 + (lane & 3) * 2;
            float* dst = g_part + ((size_t)(sp * BATCH + b) * TOPK + k0 + i0) * EDIM
                         + et * 128 + j0;
            float2 v0; v0.x = C[mt][nt][0]; v0.y = C[mt][nt][1];
            float2 v1; v1.x = C[mt][nt][2]; v1.y = C[mt][nt][3];
            *(float2*)dst = v0;
            *(float2*)(dst + (size_t)8 * EDIM) = v1;
        }
}

// ---------------------------------------------------------------------------
// K4: out = inv * sum partials
// ---------------------------------------------------------------------------
__global__ __launch_bounds__(256) void k4_reduce(float* __restrict__ out)
{
    const int idx = blockIdx.x * 256 + threadIdx.x;
    const int b = idx >> 17;
    const int k = (idx >> 9) & 255;
    const int off = idx & 0x1FFFF;
    float s = 0.f;
    #pragma unroll
    for (int sp = 0; sp < S3; sp++)
        s += g_part[((size_t)(sp * BATCH + b) << 17) + off];
    out[idx] = s * g_inv[(b << 8) | k];
}

// ---------------------------------------------------------------------------
extern "C" void kernel_launch(void* const* d_in, const int* in_sizes, int n_in,
                              void* d_out, int out_size)
{
    const float* x    = (const float*)d_in[0];
    const float* W    = (const float*)d_in[1];
    const float* bias = (const float*)d_in[2];
    float* out = (float*)d_out;
    (void)in_sizes; (void)n_in; (void)out_size;

    cudaFuncSetAttribute(k1_gemm, cudaFuncAttributeMaxDynamicSharedMemorySize, SMEM1);
    cudaFuncSetAttribute(k3_gemm, cudaFuncAttributeMaxDynamicSharedMemorySize, SMEM3);

    k0w<<<TOPK, 256>>>(W);
    k1_gemm<<<MTOT / 128, 256, SMEM1>>>(x, bias);
    k2a<<<BATCH * TOPK, 128>>>();
    k3_gemm<<<dim3(8, S3, BATCH), 256, SMEM3>>>(x);
    k4_reduce<<<(BATCH * TOPK * EDIM) / 256, 256>>>(out);
}